// round 6
// baseline (speedup 1.0000x reference)
#include <cuda_runtime.h>
#include <cstdint>
#include <math.h>

typedef unsigned long long ull;

#define BB 64
#define TT 1024
#define DD 512
#define HH 256
#define G4H 1024   // 4*H
#define KSEL 20

// ---------------- scratch (device globals; no dynamic allocation) ----------------
__device__ float g_G[(size_t)2 * TT * G4H * BB];   // [dir][t][gate*256+n][b]  (512 MB)
__device__ float g_A[(size_t)TT * DD * BB];        // [t][dir*H+n][b]          (128 MB)
__device__ float g_lstmo[(size_t)BB * TT * DD];    // [b][t][d]                (128 MB)
__device__ float g_h[2 * 2 * HH * BB];             // [dir][parity][(n>>2)*256 + b*4 + (n&3)]
__device__ float g_logits[BB * TT];                // [b][t]
__device__ unsigned g_bar;                         // step barrier counter

// output layout (float32 concat of reference tuple)
#define LN_OFF  ((size_t)1280)                            // after indices [64][20]
#define SGN_OFF ((size_t)(1280 + (size_t)BB * TT * DD))   // after lstm_o_n

// ---------------- f32x2 helpers ----------------
static __device__ __forceinline__ ull pk(float x, float y) {
    ull r;
    asm("mov.b64 %0, {%1, %2};" : "=l"(r) : "r"(__float_as_uint(x)), "r"(__float_as_uint(y)));
    return r;
}
static __device__ __forceinline__ float2 up(ull v) {
    unsigned lo, hi;
    asm("mov.b64 {%0, %1}, %2;" : "=r"(lo), "=r"(hi) : "l"(v));
    float2 r; r.x = __uint_as_float(lo); r.y = __uint_as_float(hi);
    return r;
}
static __device__ __forceinline__ ull fma2(ull a, ull b, ull c) {
    ull d;
    asm("fma.rn.f32x2 %0, %1, %2, %3;" : "=l"(d) : "l"(a), "l"(b), "l"(c));
    return d;
}
static __device__ __forceinline__ float sigm(float x) { return 1.0f / (1.0f + expf(-x)); }

// ---------------- init: zero recurrent state + barrier ----------------
__global__ void init_state_kernel() {
    int i = blockIdx.x * blockDim.x + threadIdx.x;
    if (i < 2 * 2 * HH * BB) g_h[i] = 0.0f;
    if (i == 0) g_bar = 0u;
}

// ---------------- kernel 1: input GEMM  G = X @ Wcat^T + bias ----------------
// M = 65536 (m = t*64 + b), N = 2048 (dir-concat of 4H), K = 512
__global__ void __launch_bounds__(256) gemm_xw_kernel(
    const float* __restrict__ X,
    const float* __restrict__ Wf, const float* __restrict__ Wb,
    const float* __restrict__ bf, const float* __restrict__ bb)
{
    __shared__ __align__(16) float As[16][128];
    __shared__ __align__(16) float Bs[16][64];

    const int tid = threadIdx.x;
    const int mt = blockIdx.x;         // 0..511
    const int nt = blockIdx.y;         // 0..31

    const int nx = tid & 15;
    const int my = tid >> 4;
    const int mb = my * 8;
    const int nb = nx * 4;

    const int ra0 = tid >> 2;
    const int ra1 = ra0 + 64;
    const int lkq = tid & 3;
    const int ln  = tid >> 2;

    const int m0 = mt * 128 + ra0;
    const int m1 = mt * 128 + ra1;
    const float* xr0 = X + ((size_t)(m0 & 63) * TT + (m0 >> 6)) * DD;
    const float* xr1 = X + ((size_t)(m1 & 63) * TT + (m1 >> 6)) * DD;
    const int gn_l = nt * 64 + ln;
    const float* wrow = (gn_l < 1024) ? (Wf + (size_t)gn_l * DD)
                                      : (Wb + (size_t)(gn_l - 1024) * DD);

    ull acc[4][4];
#pragma unroll
    for (int i = 0; i < 4; i++)
#pragma unroll
        for (int j = 0; j < 4; j++) acc[i][j] = 0ull;

    for (int k0 = 0; k0 < DD; k0 += 16) {
        float4 va0 = *(const float4*)(xr0 + k0 + lkq * 4);
        float4 va1 = *(const float4*)(xr1 + k0 + lkq * 4);
        float4 vb  = *(const float4*)(wrow + k0 + lkq * 4);
        __syncthreads();
        As[lkq * 4 + 0][ra0] = va0.x; As[lkq * 4 + 1][ra0] = va0.y;
        As[lkq * 4 + 2][ra0] = va0.z; As[lkq * 4 + 3][ra0] = va0.w;
        As[lkq * 4 + 0][ra1] = va1.x; As[lkq * 4 + 1][ra1] = va1.y;
        As[lkq * 4 + 2][ra1] = va1.z; As[lkq * 4 + 3][ra1] = va1.w;
        Bs[lkq * 4 + 0][ln] = vb.x; Bs[lkq * 4 + 1][ln] = vb.y;
        Bs[lkq * 4 + 2][ln] = vb.z; Bs[lkq * 4 + 3][ln] = vb.w;
        __syncthreads();
#pragma unroll
        for (int k = 0; k < 16; k++) {
            ull a01 = *(const ull*)&As[k][mb + 0];
            ull a23 = *(const ull*)&As[k][mb + 2];
            ull a45 = *(const ull*)&As[k][mb + 4];
            ull a67 = *(const ull*)&As[k][mb + 6];
            float4 bv = *(const float4*)&Bs[k][nb];
            ull b0 = pk(bv.x, bv.x), b1 = pk(bv.y, bv.y);
            ull b2 = pk(bv.z, bv.z), b3 = pk(bv.w, bv.w);
            acc[0][0] = fma2(a01, b0, acc[0][0]); acc[0][1] = fma2(a01, b1, acc[0][1]);
            acc[0][2] = fma2(a01, b2, acc[0][2]); acc[0][3] = fma2(a01, b3, acc[0][3]);
            acc[1][0] = fma2(a23, b0, acc[1][0]); acc[1][1] = fma2(a23, b1, acc[1][1]);
            acc[1][2] = fma2(a23, b2, acc[1][2]); acc[1][3] = fma2(a23, b3, acc[1][3]);
            acc[2][0] = fma2(a45, b0, acc[2][0]); acc[2][1] = fma2(a45, b1, acc[2][1]);
            acc[2][2] = fma2(a45, b2, acc[2][2]); acc[2][3] = fma2(a45, b3, acc[2][3]);
            acc[3][0] = fma2(a67, b0, acc[3][0]); acc[3][1] = fma2(a67, b1, acc[3][1]);
            acc[3][2] = fma2(a67, b2, acc[3][2]); acc[3][3] = fma2(a67, b3, acc[3][3]);
        }
    }

    // epilogue into [dir][t][col][b] layout, float2 over b (m even -> b even)
#pragma unroll
    for (int j = 0; j < 4; j++) {
        const int gn = nt * 64 + nb + j;
        const int dir = gn >> 10;
        const int col = gn & 1023;
        const float bias = dir ? bb[col] : bf[col];
#pragma unroll
        for (int i = 0; i < 4; i++) {
            const int m = mt * 128 + mb + i * 2;
            const int tq = m >> 6, bq = m & 63;
            float2 c2 = up(acc[i][j]);
            float2 o; o.x = c2.x + bias; o.y = c2.y + bias;
            *(float2*)(g_G + ((size_t)dir * TT + tq) * (size_t)(G4H * BB)
                           + (size_t)col * BB + bq) = o;
        }
    }
}

// ---------------- kernel 2: persistent recurrence ----------------
// grid 128 CTAs (dir = bid&1, grp = bid>>1 -> n0 = grp*4), 128 threads:
// warp nl = tid>>5 owns hidden col n = n0+nl; lane owns b = lane and lane+32.
__global__ void __launch_bounds__(128, 1) lstm_persist_kernel(
    const float* __restrict__ Whh_f, const float* __restrict__ Whh_b)
{
    extern __shared__ __align__(16) unsigned char sraw[];
    ulonglong2 (*Wq)[64] = (ulonglong2(*)[64])sraw;                    // [16][64] 16KB
    ulonglong2 (*hs)[64] = (ulonglong2(*)[64])(sraw + 16 * 64 * 16);   // [64][64] 64KB

    const int tid = threadIdx.x;
    const int dir = blockIdx.x & 1;
    const int grp = blockIdx.x >> 1;
    const int n0 = grp * 4;
    const int nl = tid >> 5;
    const int lane = tid & 31;
    const int n = n0 + nl;
    const float* Whh = dir ? Whh_b : Whh_f;

    // stage W_hh rows for 4 gates x 4 local cols (quad-packed over k)
    for (int i = tid; i < 16 * 64; i += 128) {
        int r = i >> 6, kq = i & 63;
        int row = (r >> 2) * HH + n0 + (r & 3);
        Wq[r][kq] = ((const ulonglong2*)(Whh + (size_t)row * HH))[kq];
    }

    float c0 = 0.0f, c1 = 0.0f;
    float pg[8];
    {
        const int t = dir ? (TT - 1) : 0;
        const float* Gs = g_G + ((size_t)dir * TT + t) * (size_t)(G4H * BB);
#pragma unroll
        for (int g = 0; g < 4; g++) {
            pg[g]     = Gs[(size_t)(g * HH + n) * BB + lane];
            pg[4 + g] = Gs[(size_t)(g * HH + n) * BB + lane + 32];
        }
    }

    for (int s = 0; s < TT; s++) {
        const int t = dir ? (TT - 1 - s) : s;

        if (s > 0) {
            if (tid == 0) {
                const unsigned tgt = 128u * (unsigned)s;
                while (*(volatile unsigned*)&g_bar < tgt) __nanosleep(64);
            }
            __syncthreads();
        }

        // stage this dir's h (parity s&1) into smem, L1-bypassed
        {
            const ulonglong2* src =
                (const ulonglong2*)(g_h + (size_t)(dir * 2 + (s & 1)) * (HH * BB));
            ulonglong2* dst = &hs[0][0];
            for (int i = tid; i < (HH * BB) / 4; i += 128)
                dst[i] = __ldcg(src + i);
        }
        __syncthreads();

        ull a0 = 0, a1 = 0, a2 = 0, a3 = 0, a4 = 0, a5 = 0, a6 = 0, a7 = 0;
        const ulonglong2* w0 = Wq[0 * 4 + nl];
        const ulonglong2* w1 = Wq[1 * 4 + nl];
        const ulonglong2* w2 = Wq[2 * 4 + nl];
        const ulonglong2* w3 = Wq[3 * 4 + nl];

#pragma unroll 4
        for (int kq = 0; kq < 64; kq++) {
            ulonglong2 h0 = hs[kq][lane];
            ulonglong2 h1 = hs[kq][lane + 32];
            ulonglong2 w;
            w = w0[kq];
            a0 = fma2(h0.x, w.x, a0); a0 = fma2(h0.y, w.y, a0);
            a4 = fma2(h1.x, w.x, a4); a4 = fma2(h1.y, w.y, a4);
            w = w1[kq];
            a1 = fma2(h0.x, w.x, a1); a1 = fma2(h0.y, w.y, a1);
            a5 = fma2(h1.x, w.x, a5); a5 = fma2(h1.y, w.y, a5);
            w = w2[kq];
            a2 = fma2(h0.x, w.x, a2); a2 = fma2(h0.y, w.y, a2);
            a6 = fma2(h1.x, w.x, a6); a6 = fma2(h1.y, w.y, a6);
            w = w3[kq];
            a3 = fma2(h0.x, w.x, a3); a3 = fma2(h0.y, w.y, a3);
            a7 = fma2(h1.x, w.x, a7); a7 = fma2(h1.y, w.y, a7);
        }

        float2 u;
        u = up(a0); const float gi0 = pg[0] + u.x + u.y;
        u = up(a1); const float gf0 = pg[1] + u.x + u.y;
        u = up(a2); const float gg0 = pg[2] + u.x + u.y;
        u = up(a3); const float go0 = pg[3] + u.x + u.y;
        u = up(a4); const float gi1 = pg[4] + u.x + u.y;
        u = up(a5); const float gf1 = pg[5] + u.x + u.y;
        u = up(a6); const float gg1 = pg[6] + u.x + u.y;
        u = up(a7); const float go1 = pg[7] + u.x + u.y;

        c0 = sigm(gf0) * c0 + sigm(gi0) * tanhf(gg0);
        const float hv0 = sigm(go0) * tanhf(c0);
        c1 = sigm(gf1) * c1 + sigm(gi1) * tanhf(gg1);
        const float hv1 = sigm(go1) * tanhf(c1);

        // write h for next step (parity (s+1)&1), quad-interleaved, L2-visible
        {
            float* hb = g_h + (size_t)(dir * 2 + ((s + 1) & 1)) * (HH * BB);
            const int base = (n >> 2) * 256 + (n & 3);
            __stcg(hb + base + lane * 4, hv0);
            __stcg(hb + base + (lane + 32) * 4, hv1);
        }
        // write output slab A[t][dir*H+n][b] (coalesced)
        {
            const size_t ab = ((size_t)t * DD + dir * HH + n) * BB;
            g_A[ab + lane] = hv0;
            g_A[ab + lane + 32] = hv1;
        }

        __threadfence();
        __syncthreads();
        if (tid == 0) atomicAdd(&g_bar, 1u);

        // prefetch next step's gate pre-activations (covered by barrier latency)
        if (s + 1 < TT) {
            const int tn = dir ? (TT - 2 - s) : (s + 1);
            const float* Gs = g_G + ((size_t)dir * TT + tn) * (size_t)(G4H * BB);
#pragma unroll
            for (int g = 0; g < 4; g++) {
                pg[g]     = Gs[(size_t)(g * HH + n) * BB + lane];
                pg[4 + g] = Gs[(size_t)(g * HH + n) * BB + lane + 32];
            }
        }
    }
}

// ---------------- kernel 2b: transpose A[t][d][b] -> lstmo[b][t][d] ----------------
__global__ void __launch_bounds__(256) transpose_kernel()
{
    __shared__ float ts[128][65];
    const int t = blockIdx.x;
    const int dblk = blockIdx.y;   // 0..3
    const int tid = threadIdx.x;

    const float* src = g_A + ((size_t)t * DD + dblk * 128) * BB;
    const int bc = tid & 63, dr0 = tid >> 6;
    for (int dr = dr0; dr < 128; dr += 4)
        ts[dr][bc] = src[(size_t)dr * BB + bc];
    __syncthreads();
    const int dc = tid & 127, br0 = tid >> 7;
    for (int br = br0; br < BB; br += 2)
        g_lstmo[((size_t)br * TT + t) * DD + dblk * 128 + dc] = ts[dc][br];
}

// ---------------- kernel 3: logits ----------------
__global__ void __launch_bounds__(256) logits_kernel(
    const float* __restrict__ lw, const float* __restrict__ lb)
{
    const int warp = threadIdx.x >> 5, lane = threadIdx.x & 31;
    const int row = blockIdx.x * 8 + warp;
    const float* xr = g_lstmo + (size_t)row * DD;
    float s = 0.0f;
#pragma unroll
    for (int q = 0; q < 4; q++) {
        int d = (lane + q * 32) * 4;
        float4 v = *(const float4*)(xr + d);
        float4 w = *(const float4*)(lw + d);
        s += v.x * w.x + v.y * w.y + v.z * w.z + v.w * w.w;
    }
#pragma unroll
    for (int o = 16; o > 0; o >>= 1) s += __shfl_xor_sync(0xffffffffu, s, o);
    if (lane == 0) g_logits[row] = s + lb[0];
}

// ---------------- kernel 4: softmax + top-20 smallest + mask ----------------
__global__ void __launch_bounds__(256) topk_mask_kernel(
    const int* __restrict__ mask, float* __restrict__ out)
{
    __shared__ float p[TT];
    __shared__ float rv[256];
    __shared__ int   ri[256];
    __shared__ int   sel[KSEL];

    const int b = blockIdx.x, tid = threadIdx.x;

    float l[4];
    float lm = -INFINITY;
#pragma unroll
    for (int q = 0; q < 4; q++) {
        l[q] = g_logits[b * TT + tid + q * 256];
        lm = fmaxf(lm, l[q]);
    }
    rv[tid] = lm; __syncthreads();
    for (int st = 128; st > 0; st >>= 1) {
        if (tid < st) rv[tid] = fmaxf(rv[tid], rv[tid + st]);
        __syncthreads();
    }
    const float mx = rv[0];
    __syncthreads();

    float ls = 0.0f;
#pragma unroll
    for (int q = 0; q < 4; q++) {
        float e = expf(l[q] - mx);
        p[tid + q * 256] = e;
        ls += e;
    }
    rv[tid] = ls; __syncthreads();
    for (int st = 128; st > 0; st >>= 1) {
        if (tid < st) rv[tid] += rv[tid + st];
        __syncthreads();
    }
    const float inv = 1.0f / rv[0];
    __syncthreads();
#pragma unroll
    for (int q = 0; q < 4; q++) p[tid + q * 256] *= inv;
    __syncthreads();

    for (int j = 0; j < KSEL; j++) {
        float bv = INFINITY; int bi = 0x7fffffff;
#pragma unroll
        for (int q = 0; q < 4; q++) {
            int tt = tid + q * 256;
            float v = p[tt];
            if (v < bv) { bv = v; bi = tt; }
        }
        rv[tid] = bv; ri[tid] = bi; __syncthreads();
        for (int st = 128; st > 0; st >>= 1) {
            if (tid < st) {
                float v2 = rv[tid + st]; int i2 = ri[tid + st];
                if (v2 < rv[tid] || (v2 == rv[tid] && i2 < ri[tid])) {
                    rv[tid] = v2; ri[tid] = i2;
                }
            }
            __syncthreads();
        }
        if (tid == 0) { sel[j] = ri[0]; p[ri[0]] = INFINITY; }
        __syncthreads();
    }

    if (tid < KSEL) out[b * KSEL + tid] = (float)sel[tid];

#pragma unroll
    for (int q = 0; q < 4; q++) {
        int tt = tid + q * 256;
        bool mk = (mask[b * TT + tt] != 0);
        bool nohit = (p[tt] != INFINITY);
        out[SGN_OFF + (size_t)b * TT + tt] = (mk && nohit) ? 1.0f : 0.0f;
    }
}

// ---------------- kernel 5: layer norm ----------------
__global__ void __launch_bounds__(256) ln_kernel(
    const float* __restrict__ lg, const float* __restrict__ lbta,
    float* __restrict__ out)
{
    const int warp = threadIdx.x >> 5, lane = threadIdx.x & 31;
    const size_t row = (size_t)blockIdx.x * 8 + warp;
    const float* xr = g_lstmo + row * DD;

    float4 v[4];
    float s = 0.0f, s2 = 0.0f;
#pragma unroll
    for (int q = 0; q < 4; q++) {
        int d = (lane + q * 32) * 4;
        v[q] = *(const float4*)(xr + d);
        s  += v[q].x + v[q].y + v[q].z + v[q].w;
        s2 += v[q].x * v[q].x + v[q].y * v[q].y + v[q].z * v[q].z + v[q].w * v[q].w;
    }
#pragma unroll
    for (int o = 16; o > 0; o >>= 1) {
        s  += __shfl_xor_sync(0xffffffffu, s, o);
        s2 += __shfl_xor_sync(0xffffffffu, s2, o);
    }
    const float mu = s * (1.0f / DD);
    float var = s2 * (1.0f / DD) - mu * mu;
    var = fmaxf(var, 0.0f);
    const float e = var + 1e-5f;
    float r = rsqrtf(e);
    r = r * (1.5f - 0.5f * e * r * r);

    float* orow = out + LN_OFF + row * DD;
#pragma unroll
    for (int q = 0; q < 4; q++) {
        int d = (lane + q * 32) * 4;
        float4 gv = *(const float4*)(lg + d);
        float4 bv = *(const float4*)(lbta + d);
        float4 y;
        y.x = (v[q].x - mu) * r * gv.x + bv.x;
        y.y = (v[q].y - mu) * r * gv.y + bv.y;
        y.z = (v[q].z - mu) * r * gv.z + bv.z;
        y.w = (v[q].w - mu) * r * gv.w + bv.w;
        *(float4*)(orow + d) = y;
    }
}

// ---------------- launch ----------------
extern "C" void kernel_launch(void* const* d_in, const int* in_sizes, int n_in,
                              void* d_out, int out_size)
{
    const float* x     = (const float*)d_in[0];
    const float* Wih_f = (const float*)d_in[1];
    const float* Whh_f = (const float*)d_in[2];
    const float* b_f   = (const float*)d_in[3];
    const float* Wih_b = (const float*)d_in[4];
    const float* Whh_b = (const float*)d_in[5];
    const float* b_b   = (const float*)d_in[6];
    const float* lin_w = (const float*)d_in[7];
    const float* lin_b = (const float*)d_in[8];
    const float* ln_g  = (const float*)d_in[9];
    const float* ln_b  = (const float*)d_in[10];
    const int*   mask  = (const int*)d_in[11];
    float* out = (float*)d_out;

    static int smem_set = 0;
    if (!smem_set) {
        cudaFuncSetAttribute(lstm_persist_kernel,
                             cudaFuncAttributeMaxDynamicSharedMemorySize, 81920);
        smem_set = 1;
    }

    init_state_kernel<<<(2 * 2 * HH * BB + 255) / 256, 256>>>();
    gemm_xw_kernel<<<dim3(512, 32), 256>>>(x, Wih_f, Wih_b, b_f, b_b);
    lstm_persist_kernel<<<128, 128, 81920>>>(Whh_f, Whh_b);
    transpose_kernel<<<dim3(TT, 4), 256>>>();
    logits_kernel<<<(BB * TT) / 8, 256>>>(lin_w, lin_b);
    topk_mask_kernel<<<BB, 256>>>(mask, out);
    ln_kernel<<<(BB * TT) / 8, 256>>>(ln_g, ln_b, out);
}

// round 7
// speedup vs baseline: 1.0935x; 1.0935x over previous
#include <cuda_runtime.h>
#include <cstdint>
#include <math.h>

typedef unsigned long long ull;

#define BB 64
#define TT 1024
#define DD 512
#define HH 256
#define G4H 1024   // 4*H
#define KSEL 20

// ---------------- scratch (device globals; no dynamic allocation) ----------------
__device__ float g_G[(size_t)2 * TT * G4H * BB];   // [dir][t][gate*256+n][b]  (512 MB)
__device__ float g_A[(size_t)TT * DD * BB];        // [t][dir*H+n][b]          (128 MB)
__device__ float g_lstmo[(size_t)BB * TT * DD];    // [b][t][d]                (128 MB)
__device__ float g_h[2 * 2 * HH * BB];             // [dir][parity][(n>>2)*256 + b*4 + (n&3)]
__device__ float g_logits[BB * TT];                // [b][t]
__device__ unsigned g_bar;                         // step barrier counter

// output layout (float32 concat of reference tuple)
#define LN_OFF  ((size_t)1280)                            // after indices [64][20]
#define SGN_OFF ((size_t)(1280 + (size_t)BB * TT * DD))   // after lstm_o_n

// ---------------- f32x2 helpers ----------------
static __device__ __forceinline__ ull pk(float x, float y) {
    ull r;
    asm("mov.b64 %0, {%1, %2};" : "=l"(r) : "r"(__float_as_uint(x)), "r"(__float_as_uint(y)));
    return r;
}
static __device__ __forceinline__ float2 up(ull v) {
    unsigned lo, hi;
    asm("mov.b64 {%0, %1}, %2;" : "=r"(lo), "=r"(hi) : "l"(v));
    float2 r; r.x = __uint_as_float(lo); r.y = __uint_as_float(hi);
    return r;
}
static __device__ __forceinline__ ull fma2(ull a, ull b, ull c) {
    ull d;
    asm("fma.rn.f32x2 %0, %1, %2, %3;" : "=l"(d) : "l"(a), "l"(b), "l"(c));
    return d;
}
static __device__ __forceinline__ float sigm(float x) { return 1.0f / (1.0f + expf(-x)); }

// ---------------- init: zero recurrent state + barrier ----------------
__global__ void init_state_kernel() {
    int i = blockIdx.x * blockDim.x + threadIdx.x;
    if (i < 2 * 2 * HH * BB) g_h[i] = 0.0f;
    if (i == 0) g_bar = 0u;
}

// ---------------- kernel 1: input GEMM  G = X @ Wcat^T + bias ----------------
// M = 65536 (m = t*64 + b), N = 2048 (dir-concat of 4H), K = 512
// grid: (nt=32, mt=512) — nt fastest so concurrent blocks share X tiles in L2.
__global__ void __launch_bounds__(256) gemm_xw_kernel(
    const float* __restrict__ X,
    const float* __restrict__ Wf, const float* __restrict__ Wb,
    const float* __restrict__ bf, const float* __restrict__ bb)
{
    __shared__ __align__(16) float As[16][128];
    __shared__ __align__(16) float Bs[16][64];

    const int tid = threadIdx.x;
    const int nt = blockIdx.x;         // 0..31
    const int mt = blockIdx.y;         // 0..511

    const int nx = tid & 15;
    const int my = tid >> 4;
    const int mb = my * 8;
    const int nb = nx * 4;

    const int ra0 = tid >> 2;
    const int ra1 = ra0 + 64;
    const int lkq = tid & 3;
    const int ln  = tid >> 2;

    const int m0 = mt * 128 + ra0;
    const int m1 = mt * 128 + ra1;
    const float* xr0 = X + ((size_t)(m0 & 63) * TT + (m0 >> 6)) * DD;
    const float* xr1 = X + ((size_t)(m1 & 63) * TT + (m1 >> 6)) * DD;
    const int gn_l = nt * 64 + ln;
    const float* wrow = (gn_l < 1024) ? (Wf + (size_t)gn_l * DD)
                                      : (Wb + (size_t)(gn_l - 1024) * DD);

    ull acc[4][4];
#pragma unroll
    for (int i = 0; i < 4; i++)
#pragma unroll
        for (int j = 0; j < 4; j++) acc[i][j] = 0ull;

    for (int k0 = 0; k0 < DD; k0 += 16) {
        float4 va0 = *(const float4*)(xr0 + k0 + lkq * 4);
        float4 va1 = *(const float4*)(xr1 + k0 + lkq * 4);
        float4 vb  = *(const float4*)(wrow + k0 + lkq * 4);
        __syncthreads();
        As[lkq * 4 + 0][ra0] = va0.x; As[lkq * 4 + 1][ra0] = va0.y;
        As[lkq * 4 + 2][ra0] = va0.z; As[lkq * 4 + 3][ra0] = va0.w;
        As[lkq * 4 + 0][ra1] = va1.x; As[lkq * 4 + 1][ra1] = va1.y;
        As[lkq * 4 + 2][ra1] = va1.z; As[lkq * 4 + 3][ra1] = va1.w;
        Bs[lkq * 4 + 0][ln] = vb.x; Bs[lkq * 4 + 1][ln] = vb.y;
        Bs[lkq * 4 + 2][ln] = vb.z; Bs[lkq * 4 + 3][ln] = vb.w;
        __syncthreads();
#pragma unroll
        for (int k = 0; k < 16; k++) {
            ull a01 = *(const ull*)&As[k][mb + 0];
            ull a23 = *(const ull*)&As[k][mb + 2];
            ull a45 = *(const ull*)&As[k][mb + 4];
            ull a67 = *(const ull*)&As[k][mb + 6];
            float4 bv = *(const float4*)&Bs[k][nb];
            ull b0 = pk(bv.x, bv.x), b1 = pk(bv.y, bv.y);
            ull b2 = pk(bv.z, bv.z), b3 = pk(bv.w, bv.w);
            acc[0][0] = fma2(a01, b0, acc[0][0]); acc[0][1] = fma2(a01, b1, acc[0][1]);
            acc[0][2] = fma2(a01, b2, acc[0][2]); acc[0][3] = fma2(a01, b3, acc[0][3]);
            acc[1][0] = fma2(a23, b0, acc[1][0]); acc[1][1] = fma2(a23, b1, acc[1][1]);
            acc[1][2] = fma2(a23, b2, acc[1][2]); acc[1][3] = fma2(a23, b3, acc[1][3]);
            acc[2][0] = fma2(a45, b0, acc[2][0]); acc[2][1] = fma2(a45, b1, acc[2][1]);
            acc[2][2] = fma2(a45, b2, acc[2][2]); acc[2][3] = fma2(a45, b3, acc[2][3]);
            acc[3][0] = fma2(a67, b0, acc[3][0]); acc[3][1] = fma2(a67, b1, acc[3][1]);
            acc[3][2] = fma2(a67, b2, acc[3][2]); acc[3][3] = fma2(a67, b3, acc[3][3]);
        }
    }

    // epilogue into [dir][t][col][b] layout, float2 over b (m even -> b even)
#pragma unroll
    for (int j = 0; j < 4; j++) {
        const int gn = nt * 64 + nb + j;
        const int dir = gn >> 10;
        const int col = gn & 1023;
        const float bias = dir ? bb[col] : bf[col];
#pragma unroll
        for (int i = 0; i < 4; i++) {
            const int m = mt * 128 + mb + i * 2;
            const int tq = m >> 6, bq = m & 63;
            float2 c2 = up(acc[i][j]);
            float2 o; o.x = c2.x + bias; o.y = c2.y + bias;
            *(float2*)(g_G + ((size_t)dir * TT + tq) * (size_t)(G4H * BB)
                           + (size_t)col * BB + bq) = o;
        }
    }
}

// ---------------- kernel 2: persistent recurrence (cp.async pipelined) ----------------
// grid 128 CTAs (dir = bid&1, grp = bid>>1 -> n0 = grp*4), 128 threads:
// warp nl = tid>>5 owns hidden col n = n0+nl; lane owns b = lane and lane+32.
__global__ void __launch_bounds__(128, 1) lstm_persist_kernel(
    const float* __restrict__ Whh_f, const float* __restrict__ Whh_b)
{
    extern __shared__ __align__(16) unsigned char sraw[];
    ulonglong2 (*Wq)[64] = (ulonglong2(*)[64])sraw;                    // [16][64] 16KB
    ulonglong2 (*hs)[64] = (ulonglong2(*)[64])(sraw + 16 * 64 * 16);   // [64][64] 64KB

    const int tid = threadIdx.x;
    const int dir = blockIdx.x & 1;
    const int grp = blockIdx.x >> 1;
    const int n0 = grp * 4;
    const int nl = tid >> 5;
    const int lane = tid & 31;
    const int n = n0 + nl;
    const float* Whh = dir ? Whh_b : Whh_f;

    const unsigned hs_base = (unsigned)__cvta_generic_to_shared(&hs[0][0]);

    // stage W_hh rows for 4 gates x 4 local cols (quad-packed over k)
    for (int i = tid; i < 16 * 64; i += 128) {
        int r = i >> 6, kq = i & 63;
        int row = (r >> 2) * HH + n0 + (r & 3);
        Wq[r][kq] = ((const ulonglong2*)(Whh + (size_t)row * HH))[kq];
    }

    float c0 = 0.0f, c1 = 0.0f;
    float pg[8];
    {
        const int t = dir ? (TT - 1) : 0;
        const float* Gs = g_G + ((size_t)dir * TT + t) * (size_t)(G4H * BB);
#pragma unroll
        for (int g = 0; g < 4; g++) {
            pg[g]     = Gs[(size_t)(g * HH + n) * BB + lane];
            pg[4 + g] = Gs[(size_t)(g * HH + n) * BB + lane + 32];
        }
    }

    const ulonglong2* w0 = Wq[0 * 4 + nl];
    const ulonglong2* w1 = Wq[1 * 4 + nl];
    const ulonglong2* w2 = Wq[2 * 4 + nl];
    const ulonglong2* w3 = Wq[3 * 4 + nl];

    for (int s = 0; s < TT; s++) {
        const int t = dir ? (TT - 1 - s) : s;

        if (s > 0) {
            if (tid == 0) {
                const unsigned tgt = 128u * (unsigned)s;
                while (*(volatile unsigned*)&g_bar < tgt) { }
            }
            __syncthreads();
        }

        // issue pipelined cp.async (L2-direct) for this dir's h (parity s&1):
        // 4 chunks x 16KB, each chunk = 16 kq rows.
        {
            const ulonglong2* src =
                (const ulonglong2*)(g_h + (size_t)(dir * 2 + (s & 1)) * (HH * BB));
#pragma unroll
            for (int c = 0; c < 4; c++) {
#pragma unroll
                for (int j = 0; j < 8; j++) {
                    const int idx = c * 1024 + j * 128 + tid;
                    asm volatile(
                        "cp.async.cg.shared.global [%0], [%1], 16;"
                        :: "r"(hs_base + idx * 16), "l"(src + idx) : "memory");
                }
                asm volatile("cp.async.commit_group;" ::: "memory");
            }
        }

        ull a0 = 0, a1 = 0, a2 = 0, a3 = 0, a4 = 0, a5 = 0, a6 = 0, a7 = 0;

#pragma unroll
        for (int c = 0; c < 4; c++) {
            if (c == 0)      asm volatile("cp.async.wait_group 3;" ::: "memory");
            else if (c == 1) asm volatile("cp.async.wait_group 2;" ::: "memory");
            else if (c == 2) asm volatile("cp.async.wait_group 1;" ::: "memory");
            else             asm volatile("cp.async.wait_group 0;" ::: "memory");
            __syncthreads();

#pragma unroll 4
            for (int kq = c * 16; kq < c * 16 + 16; kq++) {
                ulonglong2 h0 = hs[kq][lane];
                ulonglong2 h1 = hs[kq][lane + 32];
                ulonglong2 w;
                w = w0[kq];
                a0 = fma2(h0.x, w.x, a0); a0 = fma2(h0.y, w.y, a0);
                a4 = fma2(h1.x, w.x, a4); a4 = fma2(h1.y, w.y, a4);
                w = w1[kq];
                a1 = fma2(h0.x, w.x, a1); a1 = fma2(h0.y, w.y, a1);
                a5 = fma2(h1.x, w.x, a5); a5 = fma2(h1.y, w.y, a5);
                w = w2[kq];
                a2 = fma2(h0.x, w.x, a2); a2 = fma2(h0.y, w.y, a2);
                a6 = fma2(h1.x, w.x, a6); a6 = fma2(h1.y, w.y, a6);
                w = w3[kq];
                a3 = fma2(h0.x, w.x, a3); a3 = fma2(h0.y, w.y, a3);
                a7 = fma2(h1.x, w.x, a7); a7 = fma2(h1.y, w.y, a7);
            }
        }

        float2 u;
        u = up(a0); const float gi0 = pg[0] + u.x + u.y;
        u = up(a1); const float gf0 = pg[1] + u.x + u.y;
        u = up(a2); const float gg0 = pg[2] + u.x + u.y;
        u = up(a3); const float go0 = pg[3] + u.x + u.y;
        u = up(a4); const float gi1 = pg[4] + u.x + u.y;
        u = up(a5); const float gf1 = pg[5] + u.x + u.y;
        u = up(a6); const float gg1 = pg[6] + u.x + u.y;
        u = up(a7); const float go1 = pg[7] + u.x + u.y;

        c0 = sigm(gf0) * c0 + sigm(gi0) * tanhf(gg0);
        const float hv0 = sigm(go0) * tanhf(c0);
        c1 = sigm(gf1) * c1 + sigm(gi1) * tanhf(gg1);
        const float hv1 = sigm(go1) * tanhf(c1);

        // write h for next step (parity (s+1)&1), quad-interleaved, L2-visible
        {
            float* hb = g_h + (size_t)(dir * 2 + ((s + 1) & 1)) * (HH * BB);
            const int base = (n >> 2) * 256 + (n & 3);
            __stcg(hb + base + lane * 4, hv0);
            __stcg(hb + base + (lane + 32) * 4, hv1);
        }

        __threadfence();
        __syncthreads();
        if (tid == 0) atomicAdd(&g_bar, 1u);

        // post-arrival work overlaps other CTAs' barrier spin:
        // write output slab A[t][dir*H+n][b] (coalesced)
        {
            const size_t ab = ((size_t)t * DD + dir * HH + n) * BB;
            g_A[ab + lane] = hv0;
            g_A[ab + lane + 32] = hv1;
        }
        // prefetch next step's gate pre-activations
        if (s + 1 < TT) {
            const int tn = dir ? (TT - 2 - s) : (s + 1);
            const float* Gs = g_G + ((size_t)dir * TT + tn) * (size_t)(G4H * BB);
#pragma unroll
            for (int g = 0; g < 4; g++) {
                pg[g]     = Gs[(size_t)(g * HH + n) * BB + lane];
                pg[4 + g] = Gs[(size_t)(g * HH + n) * BB + lane + 32];
            }
        }
    }
}

// ---------------- kernel 2b: transpose A[t][d][b] -> lstmo[b][t][d] ----------------
__global__ void __launch_bounds__(256) transpose_kernel()
{
    __shared__ float ts[128][65];
    const int t = blockIdx.x;
    const int dblk = blockIdx.y;   // 0..3
    const int tid = threadIdx.x;

    const float* src = g_A + ((size_t)t * DD + dblk * 128) * BB;
    const int bc = tid & 63, dr0 = tid >> 6;
    for (int dr = dr0; dr < 128; dr += 4)
        ts[dr][bc] = src[(size_t)dr * BB + bc];
    __syncthreads();
    const int dc = tid & 127, br0 = tid >> 7;
    for (int br = br0; br < BB; br += 2)
        g_lstmo[((size_t)br * TT + t) * DD + dblk * 128 + dc] = ts[dc][br];
}

// ---------------- kernel 3: logits ----------------
__global__ void __launch_bounds__(256) logits_kernel(
    const float* __restrict__ lw, const float* __restrict__ lb)
{
    const int warp = threadIdx.x >> 5, lane = threadIdx.x & 31;
    const int row = blockIdx.x * 8 + warp;
    const float* xr = g_lstmo + (size_t)row * DD;
    float s = 0.0f;
#pragma unroll
    for (int q = 0; q < 4; q++) {
        int d = (lane + q * 32) * 4;
        float4 v = *(const float4*)(xr + d);
        float4 w = *(const float4*)(lw + d);
        s += v.x * w.x + v.y * w.y + v.z * w.z + v.w * w.w;
    }
#pragma unroll
    for (int o = 16; o > 0; o >>= 1) s += __shfl_xor_sync(0xffffffffu, s, o);
    if (lane == 0) g_logits[row] = s + lb[0];
}

// ---------------- kernel 4: softmax + top-20 smallest + mask ----------------
__global__ void __launch_bounds__(256) topk_mask_kernel(
    const int* __restrict__ mask, float* __restrict__ out)
{
    __shared__ float p[TT];
    __shared__ float rv[256];
    __shared__ int   ri[256];
    __shared__ int   sel[KSEL];

    const int b = blockIdx.x, tid = threadIdx.x;

    float l[4];
    float lm = -INFINITY;
#pragma unroll
    for (int q = 0; q < 4; q++) {
        l[q] = g_logits[b * TT + tid + q * 256];
        lm = fmaxf(lm, l[q]);
    }
    rv[tid] = lm; __syncthreads();
    for (int st = 128; st > 0; st >>= 1) {
        if (tid < st) rv[tid] = fmaxf(rv[tid], rv[tid + st]);
        __syncthreads();
    }
    const float mx = rv[0];
    __syncthreads();

    float ls = 0.0f;
#pragma unroll
    for (int q = 0; q < 4; q++) {
        float e = expf(l[q] - mx);
        p[tid + q * 256] = e;
        ls += e;
    }
    rv[tid] = ls; __syncthreads();
    for (int st = 128; st > 0; st >>= 1) {
        if (tid < st) rv[tid] += rv[tid + st];
        __syncthreads();
    }
    const float inv = 1.0f / rv[0];
    __syncthreads();
#pragma unroll
    for (int q = 0; q < 4; q++) p[tid + q * 256] *= inv;
    __syncthreads();

    for (int j = 0; j < KSEL; j++) {
        float bv = INFINITY; int bi = 0x7fffffff;
#pragma unroll
        for (int q = 0; q < 4; q++) {
            int tt = tid + q * 256;
            float v = p[tt];
            if (v < bv) { bv = v; bi = tt; }
        }
        rv[tid] = bv; ri[tid] = bi; __syncthreads();
        for (int st = 128; st > 0; st >>= 1) {
            if (tid < st) {
                float v2 = rv[tid + st]; int i2 = ri[tid + st];
                if (v2 < rv[tid] || (v2 == rv[tid] && i2 < ri[tid])) {
                    rv[tid] = v2; ri[tid] = i2;
                }
            }
            __syncthreads();
        }
        if (tid == 0) { sel[j] = ri[0]; p[ri[0]] = INFINITY; }
        __syncthreads();
    }

    if (tid < KSEL) out[b * KSEL + tid] = (float)sel[tid];

#pragma unroll
    for (int q = 0; q < 4; q++) {
        int tt = tid + q * 256;
        bool mk = (mask[b * TT + tt] != 0);
        bool nohit = (p[tt] != INFINITY);
        out[SGN_OFF + (size_t)b * TT + tt] = (mk && nohit) ? 1.0f : 0.0f;
    }
}

// ---------------- kernel 5: layer norm ----------------
__global__ void __launch_bounds__(256) ln_kernel(
    const float* __restrict__ lg, const float* __restrict__ lbta,
    float* __restrict__ out)
{
    const int warp = threadIdx.x >> 5, lane = threadIdx.x & 31;
    const size_t row = (size_t)blockIdx.x * 8 + warp;
    const float* xr = g_lstmo + row * DD;

    float4 v[4];
    float s = 0.0f, s2 = 0.0f;
#pragma unroll
    for (int q = 0; q < 4; q++) {
        int d = (lane + q * 32) * 4;
        v[q] = *(const float4*)(xr + d);
        s  += v[q].x + v[q].y + v[q].z + v[q].w;
        s2 += v[q].x * v[q].x + v[q].y * v[q].y + v[q].z * v[q].z + v[q].w * v[q].w;
    }
#pragma unroll
    for (int o = 16; o > 0; o >>= 1) {
        s  += __shfl_xor_sync(0xffffffffu, s, o);
        s2 += __shfl_xor_sync(0xffffffffu, s2, o);
    }
    const float mu = s * (1.0f / DD);
    float var = s2 * (1.0f / DD) - mu * mu;
    var = fmaxf(var, 0.0f);
    const float e = var + 1e-5f;
    float r = rsqrtf(e);
    r = r * (1.5f - 0.5f * e * r * r);

    float* orow = out + LN_OFF + row * DD;
#pragma unroll
    for (int q = 0; q < 4; q++) {
        int d = (lane + q * 32) * 4;
        float4 gv = *(const float4*)(lg + d);
        float4 bv = *(const float4*)(lbta + d);
        float4 y;
        y.x = (v[q].x - mu) * r * gv.x + bv.x;
        y.y = (v[q].y - mu) * r * gv.y + bv.y;
        y.z = (v[q].z - mu) * r * gv.z + bv.z;
        y.w = (v[q].w - mu) * r * gv.w + bv.w;
        *(float4*)(orow + d) = y;
    }
}

// ---------------- launch ----------------
extern "C" void kernel_launch(void* const* d_in, const int* in_sizes, int n_in,
                              void* d_out, int out_size)
{
    const float* x     = (const float*)d_in[0];
    const float* Wih_f = (const float*)d_in[1];
    const float* Whh_f = (const float*)d_in[2];
    const float* b_f   = (const float*)d_in[3];
    const float* Wih_b = (const float*)d_in[4];
    const float* Whh_b = (const float*)d_in[5];
    const float* b_b   = (const float*)d_in[6];
    const float* lin_w = (const float*)d_in[7];
    const float* lin_b = (const float*)d_in[8];
    const float* ln_g  = (const float*)d_in[9];
    const float* ln_b  = (const float*)d_in[10];
    const int*   mask  = (const int*)d_in[11];
    float* out = (float*)d_out;

    static int smem_set = 0;
    if (!smem_set) {
        cudaFuncSetAttribute(lstm_persist_kernel,
                             cudaFuncAttributeMaxDynamicSharedMemorySize, 81920);
        smem_set = 1;
    }

    init_state_kernel<<<(2 * 2 * HH * BB + 255) / 256, 256>>>();
    gemm_xw_kernel<<<dim3(32, 512), 256>>>(x, Wih_f, Wih_b, b_f, b_b);
    lstm_persist_kernel<<<128, 128, 81920>>>(Whh_f, Whh_b);
    transpose_kernel<<<dim3(TT, 4), 256>>>();
    logits_kernel<<<(BB * TT) / 8, 256>>>(lin_w, lin_b);
    topk_mask_kernel<<<BB, 256>>>(mask, out);
    ln_kernel<<<(BB * TT) / 8, 256>>>(ln_g, ln_b, out);
}

// round 11
// speedup vs baseline: 1.1367x; 1.0395x over previous
#include <cuda_runtime.h>
#include <cstdint>
#include <math.h>

typedef unsigned long long ull;

#define BB 64
#define TT 1024
#define DD 512
#define HH 256
#define G4H 1024   // 4*H
#define KSEL 20

// ---------------- scratch (device globals; no dynamic allocation) ----------------
__device__ float g_G[(size_t)2 * TT * G4H * BB];   // [dir][t][gate*256+n][b]  (512 MB)
__device__ float g_A[(size_t)TT * DD * BB];        // [t][dir*H+n][b]          (128 MB)
__device__ float g_lstmo[(size_t)BB * TT * DD];    // [b][t][d]                (128 MB)
__device__ float g_h[2 * 2 * HH * BB];             // [dir][parity][(n>>2)*256 + b*4 + (n&3)]
__device__ float g_logits[BB * TT];                // [b][t]
__device__ __align__(256) unsigned g_barA[128];    // per-dir step counters (dir*64), padded

// output layout (float32 concat of reference tuple)
#define LN_OFF  ((size_t)1280)                            // after indices [64][20]
#define SGN_OFF ((size_t)(1280 + (size_t)BB * TT * DD))   // after lstm_o_n

// ---------------- f32x2 helpers ----------------
static __device__ __forceinline__ ull pk(float x, float y) {
    ull r;
    asm("mov.b64 %0, {%1, %2};" : "=l"(r) : "r"(__float_as_uint(x)), "r"(__float_as_uint(y)));
    return r;
}
static __device__ __forceinline__ float2 up(ull v) {
    unsigned lo, hi;
    asm("mov.b64 {%0, %1}, %2;" : "=r"(lo), "=r"(hi) : "l"(v));
    float2 r; r.x = __uint_as_float(lo); r.y = __uint_as_float(hi);
    return r;
}
static __device__ __forceinline__ ull fma2(ull a, ull b, ull c) {
    ull d;
    asm("fma.rn.f32x2 %0, %1, %2, %3;" : "=l"(d) : "l"(a), "l"(b), "l"(c));
    return d;
}
static __device__ __forceinline__ float sigm(float x) { return 1.0f / (1.0f + expf(-x)); }

// ---------------- init: zero recurrent state + barriers ----------------
__global__ void init_state_kernel() {
    int i = blockIdx.x * blockDim.x + threadIdx.x;
    if (i < 2 * 2 * HH * BB) g_h[i] = 0.0f;
    if (i < 128) g_barA[i] = 0u;
}

// ---------------- kernel 1: input GEMM  G = X @ Wcat^T + bias ----------------
// M = 65536 (m = t*64 + b), N = 2048 (dir-concat of 4H), K = 512
// grid: (nt=32, mt=512) — nt fastest so concurrent blocks share X tiles in L2.
__global__ void __launch_bounds__(256) gemm_xw_kernel(
    const float* __restrict__ X,
    const float* __restrict__ Wf, const float* __restrict__ Wb,
    const float* __restrict__ bf, const float* __restrict__ bb)
{
    __shared__ __align__(16) float As[16][128];
    __shared__ __align__(16) float Bs[16][64];
    __shared__ __align__(16) float Ss[16][128];   // epilogue staging (16 cols x 128 m)

    const int tid = threadIdx.x;
    const int nt = blockIdx.x;         // 0..31
    const int mt = blockIdx.y;         // 0..511

    const int nx = tid & 15;
    const int my = tid >> 4;
    const int mb = my * 8;
    const int nb = nx * 4;

    const int ra0 = tid >> 2;
    const int ra1 = ra0 + 64;
    const int lkq = tid & 3;
    const int ln  = tid >> 2;

    const int m0 = mt * 128 + ra0;
    const int m1 = mt * 128 + ra1;
    const float* xr0 = X + ((size_t)(m0 & 63) * TT + (m0 >> 6)) * DD;
    const float* xr1 = X + ((size_t)(m1 & 63) * TT + (m1 >> 6)) * DD;
    const int gn_l = nt * 64 + ln;
    const float* wrow = (gn_l < 1024) ? (Wf + (size_t)gn_l * DD)
                                      : (Wb + (size_t)(gn_l - 1024) * DD);

    ull acc[4][4];
#pragma unroll
    for (int i = 0; i < 4; i++)
#pragma unroll
        for (int j = 0; j < 4; j++) acc[i][j] = 0ull;

    for (int k0 = 0; k0 < DD; k0 += 16) {
        float4 va0 = *(const float4*)(xr0 + k0 + lkq * 4);
        float4 va1 = *(const float4*)(xr1 + k0 + lkq * 4);
        float4 vb  = *(const float4*)(wrow + k0 + lkq * 4);
        __syncthreads();
        As[lkq * 4 + 0][ra0] = va0.x; As[lkq * 4 + 1][ra0] = va0.y;
        As[lkq * 4 + 2][ra0] = va0.z; As[lkq * 4 + 3][ra0] = va0.w;
        As[lkq * 4 + 0][ra1] = va1.x; As[lkq * 4 + 1][ra1] = va1.y;
        As[lkq * 4 + 2][ra1] = va1.z; As[lkq * 4 + 3][ra1] = va1.w;
        Bs[lkq * 4 + 0][ln] = vb.x; Bs[lkq * 4 + 1][ln] = vb.y;
        Bs[lkq * 4 + 2][ln] = vb.z; Bs[lkq * 4 + 3][ln] = vb.w;
        __syncthreads();
#pragma unroll
        for (int k = 0; k < 16; k++) {
            ull a01 = *(const ull*)&As[k][mb + 0];
            ull a23 = *(const ull*)&As[k][mb + 2];
            ull a45 = *(const ull*)&As[k][mb + 4];
            ull a67 = *(const ull*)&As[k][mb + 6];
            float4 bv = *(const float4*)&Bs[k][nb];
            ull b0 = pk(bv.x, bv.x), b1 = pk(bv.y, bv.y);
            ull b2 = pk(bv.z, bv.z), b3 = pk(bv.w, bv.w);
            acc[0][0] = fma2(a01, b0, acc[0][0]); acc[0][1] = fma2(a01, b1, acc[0][1]);
            acc[0][2] = fma2(a01, b2, acc[0][2]); acc[0][3] = fma2(a01, b3, acc[0][3]);
            acc[1][0] = fma2(a23, b0, acc[1][0]); acc[1][1] = fma2(a23, b1, acc[1][1]);
            acc[1][2] = fma2(a23, b2, acc[1][2]); acc[1][3] = fma2(a23, b3, acc[1][3]);
            acc[2][0] = fma2(a45, b0, acc[2][0]); acc[2][1] = fma2(a45, b1, acc[2][1]);
            acc[2][2] = fma2(a45, b2, acc[2][2]); acc[2][3] = fma2(a45, b3, acc[2][3]);
            acc[3][0] = fma2(a67, b0, acc[3][0]); acc[3][1] = fma2(a67, b1, acc[3][1]);
            acc[3][2] = fma2(a67, b2, acc[3][2]); acc[3][3] = fma2(a67, b3, acc[3][3]);
        }
    }

    // ---- staged epilogue: 4 passes (one per j), coalesced float4 stores ----
    const int dir = nt >> 4;                        // all 64 cols of this nt share dir
    const float* bias_p = dir ? bb : bf;
    const size_t gbase = (size_t)dir * TT * (size_t)(G4H * BB);

#pragma unroll
    for (int j = 0; j < 4; j++) {
        const int colj = nb + j;                    // local col for this thread's stores
        const float bias = bias_p[(nt * 64 + colj) & 1023];
        __syncthreads();
#pragma unroll
        for (int i = 0; i < 4; i++) {
            float2 c2 = up(acc[i][j]);
            Ss[nx][mb + i * 2 + 0] = c2.x + bias;
            Ss[nx][mb + i * 2 + 1] = c2.y + bias;
        }
        __syncthreads();
        // write 16 cols x 128 m floats = 512 float4; 2 per thread
#pragma unroll
        for (int r = 0; r < 2; r++) {
            const int idx = tid * 2 + r;            // 0..511
            const int col_l = idx >> 5;             // 0..15 (nx group)
            const int rem = idx & 31;
            const int tql = rem >> 4;               // 0..1
            const int bq = (rem & 15) * 4;          // 0..60
            const int col = nt * 64 + col_l * 4 + j;
            float4 v = *(const float4*)&Ss[col_l][tql * 64 + bq];
            *(float4*)(g_G + gbase
                       + (size_t)(mt * 2 + tql) * (size_t)(G4H * BB)
                       + (size_t)(col & 1023) * BB + bq) = v;
        }
    }
}

// ---------------- kernel 2: persistent recurrence (cp.async pipelined) ----------------
// grid 128 CTAs (dir = bid&1, grp = bid>>1 -> n0 = grp*4), 128 threads:
// warp nl = tid>>5 owns hidden col n = n0+nl; lane owns b = lane and lane+32.
__global__ void __launch_bounds__(128, 1) lstm_persist_kernel(
    const float* __restrict__ Whh_f, const float* __restrict__ Whh_b)
{
    extern __shared__ __align__(16) unsigned char sraw[];
    ulonglong2 (*Wq)[64] = (ulonglong2(*)[64])sraw;                    // [16][64] 16KB
    ulonglong2 (*hs)[64] = (ulonglong2(*)[64])(sraw + 16 * 64 * 16);   // [64][64] 64KB

    const int tid = threadIdx.x;
    const int dir = blockIdx.x & 1;
    const int grp = blockIdx.x >> 1;
    const int n0 = grp * 4;
    const int nl = tid >> 5;
    const int lane = tid & 31;
    const int n = n0 + nl;
    const float* Whh = dir ? Whh_b : Whh_f;
    unsigned* bar = &g_barA[dir * 64];

    const unsigned hs_base = (unsigned)__cvta_generic_to_shared(&hs[0][0]);

    // stage W_hh rows for 4 gates x 4 local cols (quad-packed over k)
    for (int i = tid; i < 16 * 64; i += 128) {
        int r = i >> 6, kq = i & 63;
        int row = (r >> 2) * HH + n0 + (r & 3);
        Wq[r][kq] = ((const ulonglong2*)(Whh + (size_t)row * HH))[kq];
    }

    float c0 = 0.0f, c1 = 0.0f;
    float pg[8];
    {
        const int t = dir ? (TT - 1) : 0;
        const float* Gs = g_G + ((size_t)dir * TT + t) * (size_t)(G4H * BB);
#pragma unroll
        for (int g = 0; g < 4; g++) {
            pg[g]     = Gs[(size_t)(g * HH + n) * BB + lane];
            pg[4 + g] = Gs[(size_t)(g * HH + n) * BB + lane + 32];
        }
    }

    const ulonglong2* w0 = Wq[0 * 4 + nl];
    const ulonglong2* w1 = Wq[1 * 4 + nl];
    const ulonglong2* w2 = Wq[2 * 4 + nl];
    const ulonglong2* w3 = Wq[3 * 4 + nl];

    for (int s = 0; s < TT; s++) {
        const int t = dir ? (TT - 1 - s) : s;

        if (s > 0) {
            if (tid == 0) {
                const unsigned tgt = 64u * (unsigned)s;
                unsigned v;
                do {
                    asm volatile("ld.acquire.gpu.global.u32 %0, [%1];"
                                 : "=r"(v) : "l"(bar) : "memory");
                } while (v < tgt);
            }
            __syncthreads();
        }

        // issue pipelined cp.async (L2-direct) for this dir's h (parity s&1):
        // 4 chunks x 16KB, each chunk = 16 kq rows.
        {
            const ulonglong2* src =
                (const ulonglong2*)(g_h + (size_t)(dir * 2 + (s & 1)) * (HH * BB));
#pragma unroll
            for (int c = 0; c < 4; c++) {
#pragma unroll
                for (int j = 0; j < 8; j++) {
                    const int idx = c * 1024 + j * 128 + tid;
                    asm volatile(
                        "cp.async.cg.shared.global [%0], [%1], 16;"
                        :: "r"(hs_base + idx * 16), "l"(src + idx) : "memory");
                }
                asm volatile("cp.async.commit_group;" ::: "memory");
            }
        }

        ull a0 = 0, a1 = 0, a2 = 0, a3 = 0, a4 = 0, a5 = 0, a6 = 0, a7 = 0;

#pragma unroll
        for (int c = 0; c < 4; c++) {
            if (c == 0)      asm volatile("cp.async.wait_group 3;" ::: "memory");
            else if (c == 1) asm volatile("cp.async.wait_group 2;" ::: "memory");
            else if (c == 2) asm volatile("cp.async.wait_group 1;" ::: "memory");
            else             asm volatile("cp.async.wait_group 0;" ::: "memory");
            __syncthreads();

#pragma unroll 4
            for (int kq = c * 16; kq < c * 16 + 16; kq++) {
                ulonglong2 h0 = hs[kq][lane];
                ulonglong2 h1 = hs[kq][lane + 32];
                ulonglong2 w;
                w = w0[kq];
                a0 = fma2(h0.x, w.x, a0); a0 = fma2(h0.y, w.y, a0);
                a4 = fma2(h1.x, w.x, a4); a4 = fma2(h1.y, w.y, a4);
                w = w1[kq];
                a1 = fma2(h0.x, w.x, a1); a1 = fma2(h0.y, w.y, a1);
                a5 = fma2(h1.x, w.x, a5); a5 = fma2(h1.y, w.y, a5);
                w = w2[kq];
                a2 = fma2(h0.x, w.x, a2); a2 = fma2(h0.y, w.y, a2);
                a6 = fma2(h1.x, w.x, a6); a6 = fma2(h1.y, w.y, a6);
                w = w3[kq];
                a3 = fma2(h0.x, w.x, a3); a3 = fma2(h0.y, w.y, a3);
                a7 = fma2(h1.x, w.x, a7); a7 = fma2(h1.y, w.y, a7);
            }
        }

        float2 u;
        u = up(a0); const float gi0 = pg[0] + u.x + u.y;
        u = up(a1); const float gf0 = pg[1] + u.x + u.y;
        u = up(a2); const float gg0 = pg[2] + u.x + u.y;
        u = up(a3); const float go0 = pg[3] + u.x + u.y;
        u = up(a4); const float gi1 = pg[4] + u.x + u.y;
        u = up(a5); const float gf1 = pg[5] + u.x + u.y;
        u = up(a6); const float gg1 = pg[6] + u.x + u.y;
        u = up(a7); const float go1 = pg[7] + u.x + u.y;

        c0 = sigm(gf0) * c0 + sigm(gi0) * tanhf(gg0);
        const float hv0 = sigm(go0) * tanhf(c0);
        c1 = sigm(gf1) * c1 + sigm(gi1) * tanhf(gg1);
        const float hv1 = sigm(go1) * tanhf(c1);

        // write h for next step (parity (s+1)&1), quad-interleaved, L2-visible
        {
            float* hb = g_h + (size_t)(dir * 2 + ((s + 1) & 1)) * (HH * BB);
            const int base = (n >> 2) * 256 + (n & 3);
            __stcg(hb + base + lane * 4, hv0);
            __stcg(hb + base + (lane + 32) * 4, hv1);
        }

        // publish: syncthreads orders all CTA stores; release atomic makes
        // them visible before the counter increment (no full membar needed).
        __syncthreads();
        if (tid == 0)
            asm volatile("red.release.gpu.global.add.u32 [%0], %1;"
                         :: "l"(bar), "r"(1u) : "memory");

        // post-arrival work overlaps other CTAs' barrier spin:
        {
            const size_t ab = ((size_t)t * DD + dir * HH + n) * BB;
            g_A[ab + lane] = hv0;
            g_A[ab + lane + 32] = hv1;
        }
        if (s + 1 < TT) {
            const int tn = dir ? (TT - 2 - s) : (s + 1);
            const float* Gs = g_G + ((size_t)dir * TT + tn) * (size_t)(G4H * BB);
#pragma unroll
            for (int g = 0; g < 4; g++) {
                pg[g]     = Gs[(size_t)(g * HH + n) * BB + lane];
                pg[4 + g] = Gs[(size_t)(g * HH + n) * BB + lane + 32];
            }
        }
    }
}

// ---------------- kernel 2b: transpose A[t][d][b] -> lstmo[b][t][d] ----------------
__global__ void __launch_bounds__(256) transpose_kernel()
{
    __shared__ float ts[128][65];
    const int t = blockIdx.x;
    const int dblk = blockIdx.y;   // 0..3
    const int tid = threadIdx.x;

    const float* src = g_A + ((size_t)t * DD + dblk * 128) * BB;
    const int bc = tid & 63, dr0 = tid >> 6;
    for (int dr = dr0; dr < 128; dr += 4)
        ts[dr][bc] = src[(size_t)dr * BB + bc];
    __syncthreads();
    const int dc = tid & 127, br0 = tid >> 7;
    for (int br = br0; br < BB; br += 2)
        g_lstmo[((size_t)br * TT + t) * DD + dblk * 128 + dc] = ts[dc][br];
}

// ---------------- kernel 3: logits ----------------
__global__ void __launch_bounds__(256) logits_kernel(
    const float* __restrict__ lw, const float* __restrict__ lb)
{
    const int warp = threadIdx.x >> 5, lane = threadIdx.x & 31;
    const int row = blockIdx.x * 8 + warp;
    const float* xr = g_lstmo + (size_t)row * DD;
    float s = 0.0f;
#pragma unroll
    for (int q = 0; q < 4; q++) {
        int d = (lane + q * 32) * 4;
        float4 v = *(const float4*)(xr + d);
        float4 w = *(const float4*)(lw + d);
        s += v.x * w.x + v.y * w.y + v.z * w.z + v.w * w.w;
    }
#pragma unroll
    for (int o = 16; o > 0; o >>= 1) s += __shfl_xor_sync(0xffffffffu, s, o);
    if (lane == 0) g_logits[row] = s + lb[0];
}

// ---------------- kernel 4: softmax + top-20 smallest + mask ----------------
__global__ void __launch_bounds__(256) topk_mask_kernel(
    const int* __restrict__ mask, float* __restrict__ out)
{
    __shared__ float p[TT];
    __shared__ float rv[256];
    __shared__ int   ri[256];
    __shared__ int   sel[KSEL];

    const int b = blockIdx.x, tid = threadIdx.x;

    float l[4];
    float lm = -INFINITY;
#pragma unroll
    for (int q = 0; q < 4; q++) {
        l[q] = g_logits[b * TT + tid + q * 256];
        lm = fmaxf(lm, l[q]);
    }
    rv[tid] = lm; __syncthreads();
    for (int st = 128; st > 0; st >>= 1) {
        if (tid < st) rv[tid] = fmaxf(rv[tid], rv[tid + st]);
        __syncthreads();
    }
    const float mx = rv[0];
    __syncthreads();

    float ls = 0.0f;
#pragma unroll
    for (int q = 0; q < 4; q++) {
        float e = expf(l[q] - mx);
        p[tid + q * 256] = e;
        ls += e;
    }
    rv[tid] = ls; __syncthreads();
    for (int st = 128; st > 0; st >>= 1) {
        if (tid < st) rv[tid] += rv[tid + st];
        __syncthreads();
    }
    const float inv = 1.0f / rv[0];
    __syncthreads();
#pragma unroll
    for (int q = 0; q < 4; q++) p[tid + q * 256] *= inv;
    __syncthreads();

    for (int j = 0; j < KSEL; j++) {
        float bv = INFINITY; int bi = 0x7fffffff;
#pragma unroll
        for (int q = 0; q < 4; q++) {
            int tt = tid + q * 256;
            float v = p[tt];
            if (v < bv) { bv = v; bi = tt; }
        }
        rv[tid] = bv; ri[tid] = bi; __syncthreads();
        for (int st = 128; st > 0; st >>= 1) {
            if (tid < st) {
                float v2 = rv[tid + st]; int i2 = ri[tid + st];
                if (v2 < rv[tid] || (v2 == rv[tid] && i2 < ri[tid])) {
                    rv[tid] = v2; ri[tid] = i2;
                }
            }
            __syncthreads();
        }
        if (tid == 0) { sel[j] = ri[0]; p[ri[0]] = INFINITY; }
        __syncthreads();
    }

    if (tid < KSEL) out[b * KSEL + tid] = (float)sel[tid];

#pragma unroll
    for (int q = 0; q < 4; q++) {
        int tt = tid + q * 256;
        bool mk = (mask[b * TT + tt] != 0);
        bool nohit = (p[tt] != INFINITY);
        out[SGN_OFF + (size_t)b * TT + tt] = (mk && nohit) ? 1.0f : 0.0f;
    }
}

// ---------------- kernel 5: layer norm ----------------
__global__ void __launch_bounds__(256) ln_kernel(
    const float* __restrict__ lg, const float* __restrict__ lbta,
    float* __restrict__ out)
{
    const int warp = threadIdx.x >> 5, lane = threadIdx.x & 31;
    const size_t row = (size_t)blockIdx.x * 8 + warp;
    const float* xr = g_lstmo + row * DD;

    float4 v[4];
    float s = 0.0f, s2 = 0.0f;
#pragma unroll
    for (int q = 0; q < 4; q++) {
        int d = (lane + q * 32) * 4;
        v[q] = *(const float4*)(xr + d);
        s  += v[q].x + v[q].y + v[q].z + v[q].w;
        s2 += v[q].x * v[q].x + v[q].y * v[q].y + v[q].z * v[q].z + v[q].w * v[q].w;
    }
#pragma unroll
    for (int o = 16; o > 0; o >>= 1) {
        s  += __shfl_xor_sync(0xffffffffu, s, o);
        s2 += __shfl_xor_sync(0xffffffffu, s2, o);
    }
    const float mu = s * (1.0f / DD);
    float var = s2 * (1.0f / DD) - mu * mu;
    var = fmaxf(var, 0.0f);
    const float e = var + 1e-5f;
    float r = rsqrtf(e);
    r = r * (1.5f - 0.5f * e * r * r);

    float* orow = out + LN_OFF + row * DD;
#pragma unroll
    for (int q = 0; q < 4; q++) {
        int d = (lane + q * 32) * 4;
        float4 gv = *(const float4*)(lg + d);
        float4 bv = *(const float4*)(lbta + d);
        float4 y;
        y.x = (v[q].x - mu) * r * gv.x + bv.x;
        y.y = (v[q].y - mu) * r * gv.y + bv.y;
        y.z = (v[q].z - mu) * r * gv.z + bv.z;
        y.w = (v[q].w - mu) * r * gv.w + bv.w;
        *(float4*)(orow + d) = y;
    }
}

// ---------------- launch ----------------
extern "C" void kernel_launch(void* const* d_in, const int* in_sizes, int n_in,
                              void* d_out, int out_size)
{
    const float* x     = (const float*)d_in[0];
    const float* Wih_f = (const float*)d_in[1];
    const float* Whh_f = (const float*)d_in[2];
    const float* b_f   = (const float*)d_in[3];
    const float* Wih_b = (const float*)d_in[4];
    const float* Whh_b = (const float*)d_in[5];
    const float* b_b   = (const float*)d_in[6];
    const float* lin_w = (const float*)d_in[7];
    const float* lin_b = (const float*)d_in[8];
    const float* ln_g  = (const float*)d_in[9];
    const float* ln_b  = (const float*)d_in[10];
    const int*   mask  = (const int*)d_in[11];
    float* out = (float*)d_out;

    static int smem_set = 0;
    if (!smem_set) {
        cudaFuncSetAttribute(lstm_persist_kernel,
                             cudaFuncAttributeMaxDynamicSharedMemorySize, 81920);
        smem_set = 1;
    }

    init_state_kernel<<<(2 * 2 * HH * BB + 255) / 256, 256>>>();
    gemm_xw_kernel<<<dim3(32, 512), 256>>>(x, Wih_f, Wih_b, b_f, b_b);
    lstm_persist_kernel<<<128, 128, 81920>>>(Whh_f, Whh_b);
    transpose_kernel<<<dim3(TT, 4), 256>>>();
    logits_kernel<<<(BB * TT) / 8, 256>>>(lin_w, lin_b);
    topk_mask_kernel<<<BB, 256>>>(mask, out);
    ln_kernel<<<(BB * TT) / 8, 256>>>(ln_g, ln_b, out);
}